// round 3
// baseline (speedup 1.0000x reference)
#include <cuda_runtime.h>
#include <math.h>

#define TT 2048
#define CC 2048
#define HH 16
#define DN 128
#define DR 64
#define DV 128
#define QKD 192
#define RQ 1536
#define RKV 512
#define EPSF 1e-6f
#define SCALEF 0.07216878364870323f  // 192^-0.5

// ---------------- scratch (device globals; no allocation allowed) ----------------
__device__ float g_qlat[TT * RQ];
__device__ float g_q[TT * HH * QKD];
__device__ float g_kvpe[TT * (RKV + DR)];
__device__ float g_kvlat[TT * RKV];
__device__ float g_kvb[TT * HH * (DN + DV)];
__device__ float g_y[TT * CC];
// tf32-rounded copies of inputs
__device__ float g_x[TT * CC];
__device__ float g_wqa[RQ * CC];
__device__ float g_wqb[HH * QKD * RQ];
__device__ float g_wkva[(RKV + DR) * CC];
__device__ float g_wkvb[HH * (DN + DV) * RKV];
__device__ float g_wo[CC * CC];

// ---------------- helpers ----------------
__device__ __forceinline__ float tf32r(float f) {
    unsigned u;
    asm("cvt.rna.tf32.f32 %0, %1;" : "=r"(u) : "f"(f));
    return __uint_as_float(u);
}
__device__ __forceinline__ unsigned fbits(float f) { return __float_as_uint(f); }

__device__ __forceinline__ void mma_tf32(float c[4], const unsigned a[4], const unsigned b[2]) {
    asm volatile(
        "mma.sync.aligned.m16n8k8.row.col.f32.tf32.tf32.f32 "
        "{%0,%1,%2,%3}, {%4,%5,%6,%7}, {%8,%9}, {%0,%1,%2,%3};"
        : "+f"(c[0]), "+f"(c[1]), "+f"(c[2]), "+f"(c[3])
        : "r"(a[0]), "r"(a[1]), "r"(a[2]), "r"(a[3]), "r"(b[0]), "r"(b[1]));
}

__device__ __forceinline__ void cpa16(float* s, const float* g) {
    unsigned sa = (unsigned)__cvta_generic_to_shared(s);
    asm volatile("cp.async.cg.shared.global [%0], [%1], 16;" :: "r"(sa), "l"(g) : "memory");
}
__device__ __forceinline__ void cp_commit() { asm volatile("cp.async.commit_group;" ::: "memory"); }
template <int N>
__device__ __forceinline__ void cp_wait() { asm volatile("cp.async.wait_group %0;" :: "n"(N) : "memory"); }

// ---------------- round-to-tf32 copy ----------------
__global__ void round_copy(const float* __restrict__ s, float* __restrict__ d, int n4) {
    int i = blockIdx.x * blockDim.x + threadIdx.x;
    if (i < n4) {
        float4 v = ((const float4*)s)[i];
        ((float4*)d)[i] = make_float4(tf32r(v.x), tf32r(v.y), tf32r(v.z), tf32r(v.w));
    }
}

// ---------------- tensor-core GEMM: C[M,N] = A[M,K] @ B[N,K]^T + bias ----------------
// 128x128x32 tile, 3-stage cp.async pipeline, 256 threads, warp tile 64x32.
#define GPITCH 36
#define GSTAGE (128 * GPITCH)
#define GSMEM (3 * GSTAGE * 2 * 4)

template <bool ROUND>
__global__ void __launch_bounds__(256, 2) gemm_tc(
    const float* __restrict__ A, const float* __restrict__ B,
    const float* __restrict__ bias, float* __restrict__ Cm,
    int M, int N, int K)
{
    extern __shared__ float sh[];
    float* As = sh;
    float* Bs = sh + 3 * GSTAGE;

    int tid = threadIdx.x;
    int lane = tid & 31, warp = tid >> 5;
    int wm = warp >> 2, wn = warp & 3;
    int m0 = blockIdx.y * 128, n0 = blockIdx.x * 128;

    int lr = tid >> 1;           // 0..127
    int lh = (tid & 1) << 4;     // 0 or 16 floats

    const float* Ap = A + (size_t)(m0 + lr) * K + lh;
    int nrow = n0 + lr;
    bool bv = nrow < N;
    const float* Bp = B + (size_t)(bv ? nrow : 0) * K + lh;

    auto load_stage = [&](int s, int k0) {
        float* da = As + s * GSTAGE + lr * GPITCH + lh;
        const float* ga = Ap + k0;
        cpa16(da, ga); cpa16(da + 4, ga + 4); cpa16(da + 8, ga + 8); cpa16(da + 12, ga + 12);
        float* db = Bs + s * GSTAGE + lr * GPITCH + lh;
        const float* gb = Bp + k0;
        cpa16(db, gb); cpa16(db + 4, gb + 4); cpa16(db + 8, gb + 8); cpa16(db + 12, gb + 12);
    };

    float acc[4][4][4];
#pragma unroll
    for (int i = 0; i < 4; i++)
#pragma unroll
        for (int j = 0; j < 4; j++)
#pragma unroll
            for (int k = 0; k < 4; k++) acc[i][j][k] = 0.f;

    load_stage(0, 0); cp_commit();
    load_stage(1, 32); cp_commit();

    int nIter = K >> 5;
    for (int it = 0; it < nIter; it++) {
        cp_wait<1>();
        __syncthreads();
        if (it + 2 < nIter) load_stage((it + 2) % 3, (it + 2) << 5);
        cp_commit();

        const float* Ab = As + (it % 3) * GSTAGE;
        const float* Bb = Bs + (it % 3) * GSTAGE;
#pragma unroll
        for (int ks = 0; ks < 4; ks++) {
            int kidx = ks * 8 + (lane & 3);
            unsigned af[4][4], bf[4][2];
            int arow = wm * 64 + (lane >> 2);
#pragma unroll
            for (int mf = 0; mf < 4; mf++) {
                const float* p = Ab + (arow + mf * 16) * GPITCH + kidx;
                af[mf][0] = fbits(p[0]);
                af[mf][1] = fbits(p[8 * GPITCH]);
                af[mf][2] = fbits(p[4]);
                af[mf][3] = fbits(p[8 * GPITCH + 4]);
            }
            int brow = wn * 32 + (lane >> 2);
#pragma unroll
            for (int nf = 0; nf < 4; nf++) {
                const float* p = Bb + (brow + nf * 8) * GPITCH + kidx;
                bf[nf][0] = fbits(p[0]);
                bf[nf][1] = fbits(p[4]);
            }
#pragma unroll
            for (int mf = 0; mf < 4; mf++)
#pragma unroll
                for (int nf = 0; nf < 4; nf++)
                    mma_tf32(acc[mf][nf], af[mf], bf[nf]);
        }
    }

#pragma unroll
    for (int mf = 0; mf < 4; mf++) {
        int row0 = m0 + wm * 64 + mf * 16 + (lane >> 2);
#pragma unroll
        for (int nf = 0; nf < 4; nf++) {
            int col = n0 + wn * 32 + nf * 8 + 2 * (lane & 3);
            if (col < N) {
                float b0 = bias[col], b1 = bias[col + 1];
                float v00 = acc[mf][nf][0] + b0, v01 = acc[mf][nf][1] + b1;
                float v10 = acc[mf][nf][2] + b0, v11 = acc[mf][nf][3] + b1;
                if (ROUND) { v00 = tf32r(v00); v01 = tf32r(v01); v10 = tf32r(v10); v11 = tf32r(v11); }
                *(float2*)&Cm[(size_t)row0 * N + col] = make_float2(v00, v01);
                *(float2*)&Cm[(size_t)(row0 + 8) * N + col] = make_float2(v10, v11);
            }
        }
    }
}

// ---------------- RMSNorm (row-wise), output tf32-rounded ----------------
__global__ void __launch_bounds__(256) rmsnorm_kernel(
    const float* __restrict__ src, int srcStride,
    float* __restrict__ dst, int dstStride,
    const float* __restrict__ w, int cols)
{
    int row = blockIdx.x;
    const float* s = src + (size_t)row * srcStride;
    float* d = dst + (size_t)row * dstStride;
    float sum = 0.f;
    for (int i = threadIdx.x; i < cols; i += 256) { float v = s[i]; sum += v * v; }
    __shared__ float red[256];
    red[threadIdx.x] = sum;
    __syncthreads();
    for (int o = 128; o > 0; o >>= 1) {
        if (threadIdx.x < o) red[threadIdx.x] += red[threadIdx.x + o];
        __syncthreads();
    }
    float inv = rsqrtf(red[0] / (float)cols + EPSF);
    for (int i = threadIdx.x; i < cols; i += 256) d[i] = tf32r(s[i] * inv * w[i]);
}

// ---------------- RoPE (outputs tf32-rounded) ----------------
__global__ void rope_q_kernel(const float* __restrict__ freqs) {
    int idx = blockIdx.x * blockDim.x + threadIdx.x;
    if (idx >= TT * HH * 32) return;
    int i = idx & 31;
    int h = (idx >> 5) & 15;
    int t = idx >> 9;
    float f = freqs[t * 32 + i];
    float c = cosf(f), s = sinf(f);
    float* p = g_q + (size_t)t * (HH * QKD) + h * QKD + DN + 2 * i;
    float x0 = p[0], x1 = p[1];
    p[0] = tf32r(x0 * c - x1 * s);
    p[1] = tf32r(x0 * s + x1 * c);
}

__global__ void rope_k_kernel(const float* __restrict__ freqs) {
    int idx = blockIdx.x * blockDim.x + threadIdx.x;
    if (idx >= TT * 32) return;
    int i = idx & 31;
    int t = idx >> 5;
    float f = freqs[t * 32 + i];
    float c = cosf(f), s = sinf(f);
    float* p = g_kvpe + (size_t)t * (RKV + DR) + RKV + 2 * i;
    float x0 = p[0], x1 = p[1];
    p[0] = tf32r(x0 * c - x1 * s);
    p[1] = tf32r(x0 * s + x1 * c);
}

// ---------------- Flash attention, tensor cores, cp.async double-buffered K/V ----------------
// Block = (head, 64-row q tile). 256 threads (8 warps, 4x2).
// Smem: Qs 64x192 (swizzled), Ks 2x64x192 (swizzled), Vs 2x64x128 (swizzled), Ps 64x68.
#define AQ (64 * 192)
#define AV (64 * 128)
#define APP 68
#define ATTN_FLOATS (3 * AQ + 2 * AV + 64 * APP + 192)
#define ATTN_SMEM (ATTN_FLOATS * 4)

__global__ void __launch_bounds__(256, 1) attn_tc(
    const float* __restrict__ q, const float* __restrict__ kvb,
    const float* __restrict__ kvpe, float* __restrict__ y)
{
    extern __shared__ float sm[];
    float* Qs = sm;
    float* Ks = sm + AQ;              // 2 buffers
    float* Vs = sm + 3 * AQ;          // 2 buffers
    float* Ps = sm + 3 * AQ + 2 * AV; // 64 x 68
    float* m_s = Ps + 64 * APP;
    float* l_s = m_s + 64;
    float* al_s = l_s + 64;

    int h = blockIdx.y;
    int qt = gridDim.x - 1 - blockIdx.x;   // heavy tiles first
    int tid = threadIdx.x, lane = tid & 31, warp = tid >> 5;
    int wm = warp >> 1, wn = warp & 1;

    int lr = tid >> 2;   // 0..63 (row)
    int lq = tid & 3;    // 0..3

    auto load_kv = [&](int buf, int kt2) {
        int t = kt2 * 64 + lr;
        const float* gk = kvb + (size_t)t * 4096 + h * 256;
        const float* gp = kvpe + (size_t)t * 576 + 512;
        float* Kb = Ks + buf * AQ + lr * 192;
        int sw = 4 * (lr & 7);
#pragma unroll
        for (int j = 0; j < 12; j++) {
            int c4 = lq * 12 + j;
            const float* src = (c4 < 32) ? (gk + 4 * c4) : (gp + 4 * (c4 - 32));
            cpa16(&Kb[(4 * c4) ^ sw], src);
        }
        float* Vb = Vs + buf * AV + lr * 128;
        int swv = 8 * (lr & 3);
#pragma unroll
        for (int j = 0; j < 8; j++) {
            int c4 = lq * 8 + j;
            cpa16(&Vb[(4 * c4) ^ swv], gk + 128 + 4 * c4);
        }
    };

    // prologue: Q + tile 0, one group
    {
        const float* gq = q + (size_t)(qt * 64 + lr) * (HH * QKD) + h * QKD;
        float* Qr = Qs + lr * 192;
        int sw = 4 * (lr & 7);
#pragma unroll
        for (int j = 0; j < 12; j++) {
            int c4 = lq * 12 + j;
            cpa16(&Qr[(4 * c4) ^ sw], gq + 4 * c4);
        }
    }
    load_kv(0, 0);
    cp_commit();

    if (tid < 64) { m_s[tid] = -1e30f; l_s[tid] = 0.f; }

    float oacc[8][4];
#pragma unroll
    for (int i = 0; i < 8; i++)
#pragma unroll
        for (int j = 0; j < 4; j++) oacc[i][j] = 0.f;

    for (int kt = 0; kt <= qt; kt++) {
        cp_wait<0>();
        __syncthreads();
        if (kt < qt) load_kv((kt + 1) & 1, kt + 1);
        cp_commit();

        const float* Kb = Ks + (kt & 1) * AQ;
        const float* Vb = Vs + (kt & 1) * AV;

        // ---- S = Q K^T (warp tile 16x32) ----
        float sacc[4][4];
#pragma unroll
        for (int i = 0; i < 4; i++)
#pragma unroll
            for (int j = 0; j < 4; j++) sacc[i][j] = 0.f;

        {
            int r0 = wm * 16 + (lane >> 2);
            int swa = 4 * ((lane >> 2) & 7);
            const float* Aq0 = Qs + r0 * 192;
            const float* Aq8 = Qs + (r0 + 8) * 192;
#pragma unroll 4
            for (int k0 = 0; k0 < QKD; k0 += 8) {
                int k = k0 + (lane & 3);
                unsigned a[4];
                a[0] = fbits(Aq0[k ^ swa]);
                a[1] = fbits(Aq8[k ^ swa]);
                a[2] = fbits(Aq0[(k + 4) ^ swa]);
                a[3] = fbits(Aq8[(k + 4) ^ swa]);
#pragma unroll
                for (int nf = 0; nf < 4; nf++) {
                    const float* pb = Kb + (wn * 32 + nf * 8 + (lane >> 2)) * 192;
                    unsigned b[2] = { fbits(pb[k ^ swa]), fbits(pb[(k + 4) ^ swa]) };
                    mma_tf32(sacc[nf], a, b);
                }
            }
        }
#pragma unroll
        for (int nf = 0; nf < 4; nf++) {
            int r = wm * 16 + (lane >> 2);
            int c = wn * 32 + nf * 8 + 2 * (lane & 3);
            Ps[r * APP + c] = sacc[nf][0];
            Ps[r * APP + c + 1] = sacc[nf][1];
            Ps[(r + 8) * APP + c] = sacc[nf][2];
            Ps[(r + 8) * APP + c + 1] = sacc[nf][3];
        }
        __syncthreads();

        // ---- online softmax (scale applied in exponent) ----
        {
            int row = tid >> 2, sub = tid & 3;
            float* pr = Ps + row * APP + sub * 16;
            bool diag = (kt == qt);
            float v[16];
#pragma unroll
            for (int j = 0; j < 16; j++) {
                float x = pr[j];
                if (diag && (sub * 16 + j) > row) x = -1e30f;
                v[j] = x;
            }
            float mx = v[0];
#pragma unroll
            for (int j = 1; j < 16; j++) mx = fmaxf(mx, v[j]);
            mx = fmaxf(mx, __shfl_xor_sync(0xffffffffu, mx, 1));
            mx = fmaxf(mx, __shfl_xor_sync(0xffffffffu, mx, 2));
            float mo = m_s[row];
            float mn = fmaxf(mo, mx);
            float sum = 0.f;
#pragma unroll
            for (int j = 0; j < 16; j++) {
                float p = __expf((v[j] - mn) * SCALEF);
                sum += p;
                pr[j] = tf32r(p);
            }
            sum += __shfl_xor_sync(0xffffffffu, sum, 1);
            sum += __shfl_xor_sync(0xffffffffu, sum, 2);
            if (sub == 0) {
                float al = __expf((mo - mn) * SCALEF);
                al_s[row] = al;
                l_s[row] = l_s[row] * al + sum;
                m_s[row] = mn;
            }
        }
        __syncthreads();

        // ---- O = O*alpha + P V (warp tile 16x64) ----
        {
            int r0 = wm * 16 + (lane >> 2);
            float al0 = al_s[r0], al1 = al_s[r0 + 8];
#pragma unroll
            for (int nf = 0; nf < 8; nf++) {
                oacc[nf][0] *= al0; oacc[nf][1] *= al0;
                oacc[nf][2] *= al1; oacc[nf][3] *= al1;
            }
            const float* Ap0 = Ps + r0 * APP + (lane & 3);
            int swv = 8 * (lane & 3);
#pragma unroll
            for (int k0 = 0; k0 < 64; k0 += 8) {
                unsigned a[4];
                a[0] = fbits(Ap0[k0]);
                a[1] = fbits(Ap0[k0 + 8 * APP]);
                a[2] = fbits(Ap0[k0 + 4]);
                a[3] = fbits(Ap0[k0 + 4 + 8 * APP]);
                int kr = k0 + (lane & 3);
                const float* Vr0 = Vb + kr * 128;
                const float* Vr4 = Vb + (kr + 4) * 128;
#pragma unroll
                for (int nf = 0; nf < 8; nf++) {
                    int col = wn * 64 + nf * 8 + (lane >> 2);
                    unsigned b[2] = { fbits(Vr0[col ^ swv]), fbits(Vr4[col ^ swv]) };
                    mma_tf32(oacc[nf], a, b);
                }
            }
        }
    }

    // epilogue: divide by l, write y tf32-rounded (feeds final GEMM)
    {
        int r0 = wm * 16 + (lane >> 2);
        float inv0 = 1.f / l_s[r0], inv1 = 1.f / l_s[r0 + 8];
        int t0 = qt * 64 + r0;
#pragma unroll
        for (int nf = 0; nf < 8; nf++) {
            int c = wn * 64 + nf * 8 + 2 * (lane & 3);
            float* y0 = y + (size_t)t0 * CC + h * DV + c;
            float* y1 = y + (size_t)(t0 + 8) * CC + h * DV + c;
            y0[0] = tf32r(oacc[nf][0] * inv0);
            y0[1] = tf32r(oacc[nf][1] * inv0);
            y1[0] = tf32r(oacc[nf][2] * inv1);
            y1[1] = tf32r(oacc[nf][3] * inv1);
        }
    }
}

// ---------------- launch ----------------
extern "C" void kernel_launch(void* const* d_in, const int* in_sizes, int n_in,
                              void* d_out, int out_size) {
    const float* x        = (const float*)d_in[0];
    const float* freqs    = (const float*)d_in[1];
    const float* wq_a     = (const float*)d_in[2];
    const float* bq_a     = (const float*)d_in[3];
    const float* q_norm_w = (const float*)d_in[4];
    const float* wq_b     = (const float*)d_in[5];
    const float* bq_b     = (const float*)d_in[6];
    const float* wkv_a    = (const float*)d_in[7];
    const float* bkv_a    = (const float*)d_in[8];
    const float* kv_norm_w= (const float*)d_in[9];
    const float* wkv_b    = (const float*)d_in[10];
    const float* bkv_b    = (const float*)d_in[11];
    const float* wo       = (const float*)d_in[12];
    const float* bo       = (const float*)d_in[13];
    float* out = (float*)d_out;

    float *qlat, *qbuf, *kvpe, *kvlat, *kvb, *ybuf;
    float *gx, *gwqa, *gwqb, *gwkva, *gwkvb, *gwo;
    cudaGetSymbolAddress((void**)&qlat,  g_qlat);
    cudaGetSymbolAddress((void**)&qbuf,  g_q);
    cudaGetSymbolAddress((void**)&kvpe,  g_kvpe);
    cudaGetSymbolAddress((void**)&kvlat, g_kvlat);
    cudaGetSymbolAddress((void**)&kvb,   g_kvb);
    cudaGetSymbolAddress((void**)&ybuf,  g_y);
    cudaGetSymbolAddress((void**)&gx,    g_x);
    cudaGetSymbolAddress((void**)&gwqa,  g_wqa);
    cudaGetSymbolAddress((void**)&gwqb,  g_wqb);
    cudaGetSymbolAddress((void**)&gwkva, g_wkva);
    cudaGetSymbolAddress((void**)&gwkvb, g_wkvb);
    cudaGetSymbolAddress((void**)&gwo,   g_wo);

    cudaFuncSetAttribute(gemm_tc<false>, cudaFuncAttributeMaxDynamicSharedMemorySize, GSMEM);
    cudaFuncSetAttribute(gemm_tc<true>,  cudaFuncAttributeMaxDynamicSharedMemorySize, GSMEM);
    cudaFuncSetAttribute(attn_tc, cudaFuncAttributeMaxDynamicSharedMemorySize, ATTN_SMEM);

    // tf32-round inputs once per launch
    round_copy<<<(TT * CC / 4 + 255) / 256, 256>>>(x, gx, TT * CC / 4);
    round_copy<<<(RQ * CC / 4 + 255) / 256, 256>>>(wq_a, gwqa, RQ * CC / 4);
    round_copy<<<(HH * QKD * RQ / 4 + 255) / 256, 256>>>(wq_b, gwqb, HH * QKD * RQ / 4);
    round_copy<<<((RKV + DR) * CC / 4 + 255) / 256, 256>>>(wkv_a, gwkva, (RKV + DR) * CC / 4);
    round_copy<<<(HH * (DN + DV) * RKV / 4 + 255) / 256, 256>>>(wkv_b, gwkvb, HH * (DN + DV) * RKV / 4);
    round_copy<<<(CC * CC / 4 + 255) / 256, 256>>>(wo, gwo, CC * CC / 4);

    // Q path
    gemm_tc<false><<<dim3(RQ / 128, TT / 128), 256, GSMEM>>>(gx, gwqa, bq_a, qlat, TT, RQ, CC);
    rmsnorm_kernel<<<TT, 256>>>(qlat, RQ, qlat, RQ, q_norm_w, RQ);
    gemm_tc<true><<<dim3((HH * QKD) / 128, TT / 128), 256, GSMEM>>>(qlat, gwqb, bq_b, qbuf, TT, HH * QKD, RQ);
    rope_q_kernel<<<(TT * HH * 32 + 255) / 256, 256>>>(freqs);

    // KV path
    gemm_tc<false><<<dim3((RKV + DR + 127) / 128, TT / 128), 256, GSMEM>>>(gx, gwkva, bkv_a, kvpe, TT, RKV + DR, CC);
    rope_k_kernel<<<(TT * 32 + 255) / 256, 256>>>(freqs);
    rmsnorm_kernel<<<TT, 256>>>(kvpe, RKV + DR, kvlat, RKV, kv_norm_w, RKV);
    gemm_tc<true><<<dim3((HH * 256) / 128, TT / 128), 256, GSMEM>>>(kvlat, gwkvb, bkv_b, kvb, TT, HH * 256, RKV);

    // Attention
    attn_tc<<<dim3(TT / 64, HH), 256, ATTN_SMEM>>>(qbuf, kvb, kvpe, ybuf);

    // Output projection
    gemm_tc<false><<<dim3(CC / 128, TT / 128), 256, GSMEM>>>(ybuf, gwo, bo, out, TT, CC, CC);
}

// round 4
// speedup vs baseline: 1.1253x; 1.1253x over previous
#include <cuda_runtime.h>
#include <math.h>

#define TT 2048
#define CC 2048
#define HH 16
#define DN 128
#define DR 64
#define DV 128
#define QKD 192
#define RQ 1536
#define RKV 512
#define EPSF 1e-6f
#define SCALEF 0.07216878364870323f  // 192^-0.5

// ---------------- scratch (device globals; no allocation allowed) ----------------
__device__ float g_qlat[TT * RQ];
__device__ float g_q[TT * HH * QKD];
__device__ float g_kvpe[TT * (RKV + DR)];
__device__ float g_kvlat[TT * RKV];
__device__ float g_kvb[TT * HH * (DN + DV)];
__device__ float g_y[TT * CC];

// ---------------- helpers ----------------
__device__ __forceinline__ float tf32r(float f) {
    unsigned u;
    asm("cvt.rna.tf32.f32 %0, %1;" : "=r"(u) : "f"(f));
    return __uint_as_float(u);
}
__device__ __forceinline__ unsigned fbits(float f) { return __float_as_uint(f); }
__device__ __forceinline__ unsigned ldt(const float* p) { return fbits(tf32r(*p)); }

__device__ __forceinline__ void mma_tf32(float c[4], const unsigned a[4], const unsigned b[2]) {
    asm volatile(
        "mma.sync.aligned.m16n8k8.row.col.f32.tf32.tf32.f32 "
        "{%0,%1,%2,%3}, {%4,%5,%6,%7}, {%8,%9}, {%0,%1,%2,%3};"
        : "+f"(c[0]), "+f"(c[1]), "+f"(c[2]), "+f"(c[3])
        : "r"(a[0]), "r"(a[1]), "r"(a[2]), "r"(a[3]), "r"(b[0]), "r"(b[1]));
}

__device__ __forceinline__ void cpa16(float* s, const float* g) {
    unsigned sa = (unsigned)__cvta_generic_to_shared(s);
    asm volatile("cp.async.cg.shared.global [%0], [%1], 16;" :: "r"(sa), "l"(g) : "memory");
}
__device__ __forceinline__ void cp_commit() { asm volatile("cp.async.commit_group;" ::: "memory"); }
template <int N>
__device__ __forceinline__ void cp_wait() { asm volatile("cp.async.wait_group %0;" :: "n"(N) : "memory"); }

// ---------------- tensor-core GEMM: C[M,N] = A[M,K] @ B[N,K]^T + bias ----------------
// Tile (32*MF) x (32*NF) x 32, 3-stage cp.async pipeline, 256 threads (2x4 warps).
// tf32 rounding applied at fragment-load time (cvt.rna), raw f32 in smem.
#define GPIT 36

template <int MF, int NF>
__global__ void __launch_bounds__(256, 2) gemm_tc(
    const float* __restrict__ A, const float* __restrict__ B,
    const float* __restrict__ bias, float* __restrict__ Cm,
    int K)
{
    constexpr int BM = 32 * MF, BN = 32 * NF;
    constexpr int ASTAGE = BM * GPIT, BSTAGE = BN * GPIT;

    extern __shared__ float sh[];
    float* As = sh;
    float* Bs = sh + 3 * ASTAGE;

    int tid = threadIdx.x;
    int lane = tid & 31, warp = tid >> 5;
    int wm = warp >> 2, wn = warp & 3;
    int m0 = blockIdx.y * BM, n0 = blockIdx.x * BN;
    int N = gridDim.x * BN;

    auto load_stage = [&](int s, int k0) {
#pragma unroll
        for (int i = 0; i < BM * 8; i += 256) {
            int idx = i + tid, r = idx >> 3, c = (idx & 7) << 2;
            cpa16(As + s * ASTAGE + r * GPIT + c, A + (size_t)(m0 + r) * K + k0 + c);
        }
#pragma unroll
        for (int i = 0; i < BN * 8; i += 256) {
            int idx = i + tid, r = idx >> 3, c = (idx & 7) << 2;
            cpa16(Bs + s * BSTAGE + r * GPIT + c, B + (size_t)(n0 + r) * K + k0 + c);
        }
    };

    float acc[MF][NF][4];
#pragma unroll
    for (int i = 0; i < MF; i++)
#pragma unroll
        for (int j = 0; j < NF; j++)
#pragma unroll
            for (int k = 0; k < 4; k++) acc[i][j][k] = 0.f;

    load_stage(0, 0); cp_commit();
    load_stage(1, 32); cp_commit();

    int nIter = K >> 5;
    for (int it = 0; it < nIter; it++) {
        cp_wait<1>();
        __syncthreads();
        if (it + 2 < nIter) load_stage((it + 2) % 3, (it + 2) << 5);
        cp_commit();

        const float* Ab = As + (it % 3) * ASTAGE;
        const float* Bb = Bs + (it % 3) * BSTAGE;
#pragma unroll
        for (int ks = 0; ks < 4; ks++) {
            int kidx = ks * 8 + (lane & 3);
            unsigned af[MF][4], bf[NF][2];
            int arow = wm * (MF * 16) + (lane >> 2);
#pragma unroll
            for (int mf = 0; mf < MF; mf++) {
                const float* p = Ab + (arow + mf * 16) * GPIT + kidx;
                af[mf][0] = ldt(p);
                af[mf][1] = ldt(p + 8 * GPIT);
                af[mf][2] = ldt(p + 4);
                af[mf][3] = ldt(p + 8 * GPIT + 4);
            }
            int brow = wn * (NF * 8) + (lane >> 2);
#pragma unroll
            for (int nf = 0; nf < NF; nf++) {
                const float* p = Bb + (brow + nf * 8) * GPIT + kidx;
                bf[nf][0] = ldt(p);
                bf[nf][1] = ldt(p + 4);
            }
#pragma unroll
            for (int mf = 0; mf < MF; mf++)
#pragma unroll
                for (int nf = 0; nf < NF; nf++)
                    mma_tf32(acc[mf][nf], af[mf], bf[nf]);
        }
    }

#pragma unroll
    for (int mf = 0; mf < MF; mf++) {
        int row0 = m0 + wm * (MF * 16) + mf * 16 + (lane >> 2);
#pragma unroll
        for (int nf = 0; nf < NF; nf++) {
            int col = n0 + wn * (NF * 8) + nf * 8 + 2 * (lane & 3);
            float b0 = bias[col], b1 = bias[col + 1];
            *(float2*)&Cm[(size_t)row0 * N + col] =
                make_float2(acc[mf][nf][0] + b0, acc[mf][nf][1] + b1);
            *(float2*)&Cm[(size_t)(row0 + 8) * N + col] =
                make_float2(acc[mf][nf][2] + b0, acc[mf][nf][3] + b1);
        }
    }
}

// ---------------- RMSNorm (row-wise) ----------------
__global__ void __launch_bounds__(256) rmsnorm_kernel(
    const float* __restrict__ src, int srcStride,
    float* __restrict__ dst, int dstStride,
    const float* __restrict__ w, int cols)
{
    int row = blockIdx.x;
    const float* s = src + (size_t)row * srcStride;
    float* d = dst + (size_t)row * dstStride;
    float sum = 0.f;
    for (int i = threadIdx.x; i < cols; i += 256) { float v = s[i]; sum += v * v; }
    __shared__ float red[256];
    red[threadIdx.x] = sum;
    __syncthreads();
    for (int o = 128; o > 0; o >>= 1) {
        if (threadIdx.x < o) red[threadIdx.x] += red[threadIdx.x + o];
        __syncthreads();
    }
    float inv = rsqrtf(red[0] / (float)cols + EPSF);
    for (int i = threadIdx.x; i < cols; i += 256) d[i] = s[i] * inv * w[i];
}

// ---------------- RoPE ----------------
__global__ void rope_q_kernel(const float* __restrict__ freqs) {
    int idx = blockIdx.x * blockDim.x + threadIdx.x;
    if (idx >= TT * HH * 32) return;
    int i = idx & 31;
    int h = (idx >> 5) & 15;
    int t = idx >> 9;
    float f = freqs[t * 32 + i];
    float c = cosf(f), s = sinf(f);
    float* p = g_q + (size_t)t * (HH * QKD) + h * QKD + DN + 2 * i;
    float x0 = p[0], x1 = p[1];
    p[0] = x0 * c - x1 * s;
    p[1] = x0 * s + x1 * c;
}

__global__ void rope_k_kernel(const float* __restrict__ freqs) {
    int idx = blockIdx.x * blockDim.x + threadIdx.x;
    if (idx >= TT * 32) return;
    int i = idx & 31;
    int t = idx >> 5;
    float f = freqs[t * 32 + i];
    float c = cosf(f), s = sinf(f);
    float* p = g_kvpe + (size_t)t * (RKV + DR) + RKV + 2 * i;
    float x0 = p[0], x1 = p[1];
    p[0] = x0 * c - x1 * s;
    p[1] = x0 * s + x1 * c;
}

// ---------------- Flash attention, tensor cores, cp.async double-buffered K/V ----------------
#define AQ (64 * 192)
#define AV (64 * 128)
#define APP 68
#define ATTN_FLOATS (3 * AQ + 2 * AV + 64 * APP + 192)
#define ATTN_SMEM (ATTN_FLOATS * 4)

__global__ void __launch_bounds__(256, 1) attn_tc(
    const float* __restrict__ q, const float* __restrict__ kvb,
    const float* __restrict__ kvpe, float* __restrict__ y)
{
    extern __shared__ float sm[];
    float* Qs = sm;
    float* Ks = sm + AQ;              // 2 buffers
    float* Vs = sm + 3 * AQ;          // 2 buffers
    float* Ps = sm + 3 * AQ + 2 * AV; // 64 x 68
    float* m_s = Ps + 64 * APP;
    float* l_s = m_s + 64;
    float* al_s = l_s + 64;

    int h = blockIdx.y;
    int qt = gridDim.x - 1 - blockIdx.x;   // heavy tiles first
    int tid = threadIdx.x, lane = tid & 31, warp = tid >> 5;
    int wm = warp >> 1, wn = warp & 1;

    int lr = tid >> 2;   // 0..63 (row)
    int lq = tid & 3;    // 0..3

    auto load_kv = [&](int buf, int kt2) {
        int t = kt2 * 64 + lr;
        const float* gk = kvb + (size_t)t * 4096 + h * 256;
        const float* gp = kvpe + (size_t)t * 576 + 512;
        float* Kb = Ks + buf * AQ + lr * 192;
        int sw = 4 * (lr & 7);
#pragma unroll
        for (int j = 0; j < 12; j++) {
            int c4 = lq * 12 + j;
            const float* src = (c4 < 32) ? (gk + 4 * c4) : (gp + 4 * (c4 - 32));
            cpa16(&Kb[(4 * c4) ^ sw], src);
        }
        float* Vb = Vs + buf * AV + lr * 128;
        int swv = 8 * (lr & 3);
#pragma unroll
        for (int j = 0; j < 8; j++) {
            int c4 = lq * 8 + j;
            cpa16(&Vb[(4 * c4) ^ swv], gk + 128 + 4 * c4);
        }
    };

    // prologue: Q + tile 0, one group
    {
        const float* gq = q + (size_t)(qt * 64 + lr) * (HH * QKD) + h * QKD;
        float* Qr = Qs + lr * 192;
        int sw = 4 * (lr & 7);
#pragma unroll
        for (int j = 0; j < 12; j++) {
            int c4 = lq * 12 + j;
            cpa16(&Qr[(4 * c4) ^ sw], gq + 4 * c4);
        }
    }
    load_kv(0, 0);
    cp_commit();

    if (tid < 64) { m_s[tid] = -1e30f; l_s[tid] = 0.f; }

    float oacc[8][4];
#pragma unroll
    for (int i = 0; i < 8; i++)
#pragma unroll
        for (int j = 0; j < 4; j++) oacc[i][j] = 0.f;

    for (int kt = 0; kt <= qt; kt++) {
        cp_wait<0>();
        __syncthreads();
        if (kt < qt) load_kv((kt + 1) & 1, kt + 1);
        cp_commit();

        const float* Kb = Ks + (kt & 1) * AQ;
        const float* Vb = Vs + (kt & 1) * AV;

        // ---- S = Q K^T (warp tile 16x32) ----
        float sacc[4][4];
#pragma unroll
        for (int i = 0; i < 4; i++)
#pragma unroll
            for (int j = 0; j < 4; j++) sacc[i][j] = 0.f;

        {
            int r0 = wm * 16 + (lane >> 2);
            int swa = 4 * ((lane >> 2) & 7);
            const float* Aq0 = Qs + r0 * 192;
            const float* Aq8 = Qs + (r0 + 8) * 192;
#pragma unroll 4
            for (int k0 = 0; k0 < QKD; k0 += 8) {
                int k = k0 + (lane & 3);
                unsigned a[4];
                a[0] = ldt(&Aq0[k ^ swa]);
                a[1] = ldt(&Aq8[k ^ swa]);
                a[2] = ldt(&Aq0[(k + 4) ^ swa]);
                a[3] = ldt(&Aq8[(k + 4) ^ swa]);
#pragma unroll
                for (int nf = 0; nf < 4; nf++) {
                    const float* pb = Kb + (wn * 32 + nf * 8 + (lane >> 2)) * 192;
                    unsigned b[2] = { ldt(&pb[k ^ swa]), ldt(&pb[(k + 4) ^ swa]) };
                    mma_tf32(sacc[nf], a, b);
                }
            }
        }
#pragma unroll
        for (int nf = 0; nf < 4; nf++) {
            int r = wm * 16 + (lane >> 2);
            int c = wn * 32 + nf * 8 + 2 * (lane & 3);
            Ps[r * APP + c] = sacc[nf][0];
            Ps[r * APP + c + 1] = sacc[nf][1];
            Ps[(r + 8) * APP + c] = sacc[nf][2];
            Ps[(r + 8) * APP + c + 1] = sacc[nf][3];
        }
        __syncthreads();

        // ---- online softmax (scale applied in exponent) ----
        {
            int row = tid >> 2, sub = tid & 3;
            float* pr = Ps + row * APP + sub * 16;
            bool diag = (kt == qt);
            float v[16];
#pragma unroll
            for (int j = 0; j < 16; j++) {
                float x = pr[j];
                if (diag && (sub * 16 + j) > row) x = -1e30f;
                v[j] = x;
            }
            float mx = v[0];
#pragma unroll
            for (int j = 1; j < 16; j++) mx = fmaxf(mx, v[j]);
            mx = fmaxf(mx, __shfl_xor_sync(0xffffffffu, mx, 1));
            mx = fmaxf(mx, __shfl_xor_sync(0xffffffffu, mx, 2));
            float mo = m_s[row];
            float mn = fmaxf(mo, mx);
            float sum = 0.f;
#pragma unroll
            for (int j = 0; j < 16; j++) {
                float p = __expf((v[j] - mn) * SCALEF);
                sum += p;
                pr[j] = tf32r(p);
            }
            sum += __shfl_xor_sync(0xffffffffu, sum, 1);
            sum += __shfl_xor_sync(0xffffffffu, sum, 2);
            if (sub == 0) {
                float al = __expf((mo - mn) * SCALEF);
                al_s[row] = al;
                l_s[row] = l_s[row] * al + sum;
                m_s[row] = mn;
            }
        }
        __syncthreads();

        // ---- O = O*alpha + P V (warp tile 16x64) ----
        {
            int r0 = wm * 16 + (lane >> 2);
            float al0 = al_s[r0], al1 = al_s[r0 + 8];
#pragma unroll
            for (int nf = 0; nf < 8; nf++) {
                oacc[nf][0] *= al0; oacc[nf][1] *= al0;
                oacc[nf][2] *= al1; oacc[nf][3] *= al1;
            }
            const float* Ap0 = Ps + r0 * APP + (lane & 3);
            int swv = 8 * (lane & 3);
#pragma unroll
            for (int k0 = 0; k0 < 64; k0 += 8) {
                unsigned a[4];
                a[0] = fbits(Ap0[k0]);
                a[1] = fbits(Ap0[k0 + 8 * APP]);
                a[2] = fbits(Ap0[k0 + 4]);
                a[3] = fbits(Ap0[k0 + 4 + 8 * APP]);
                int kr = k0 + (lane & 3);
                const float* Vr0 = Vb + kr * 128;
                const float* Vr4 = Vb + (kr + 4) * 128;
#pragma unroll
                for (int nf = 0; nf < 8; nf++) {
                    int col = wn * 64 + nf * 8 + (lane >> 2);
                    unsigned b[2] = { ldt(&Vr0[col ^ swv]), ldt(&Vr4[col ^ swv]) };
                    mma_tf32(oacc[nf], a, b);
                }
            }
        }
    }

    // epilogue: divide by l, write y
    {
        int r0 = wm * 16 + (lane >> 2);
        float inv0 = 1.f / l_s[r0], inv1 = 1.f / l_s[r0 + 8];
        int t0 = qt * 64 + r0;
#pragma unroll
        for (int nf = 0; nf < 8; nf++) {
            int c = wn * 64 + nf * 8 + 2 * (lane & 3);
            float* y0 = y + (size_t)t0 * CC + h * DV + c;
            float* y1 = y + (size_t)(t0 + 8) * CC + h * DV + c;
            y0[0] = oacc[nf][0] * inv0;
            y0[1] = oacc[nf][1] * inv0;
            y1[0] = oacc[nf][2] * inv1;
            y1[1] = oacc[nf][3] * inv1;
        }
    }
}

// ---------------- launch ----------------
static inline int gsmem(int MF, int NF) { return 3 * (32 * MF + 32 * NF) * GPIT * 4; }

extern "C" void kernel_launch(void* const* d_in, const int* in_sizes, int n_in,
                              void* d_out, int out_size) {
    const float* x        = (const float*)d_in[0];
    const float* freqs    = (const float*)d_in[1];
    const float* wq_a     = (const float*)d_in[2];
    const float* bq_a     = (const float*)d_in[3];
    const float* q_norm_w = (const float*)d_in[4];
    const float* wq_b     = (const float*)d_in[5];
    const float* bq_b     = (const float*)d_in[6];
    const float* wkv_a    = (const float*)d_in[7];
    const float* bkv_a    = (const float*)d_in[8];
    const float* kv_norm_w= (const float*)d_in[9];
    const float* wkv_b    = (const float*)d_in[10];
    const float* bkv_b    = (const float*)d_in[11];
    const float* wo       = (const float*)d_in[12];
    const float* bo       = (const float*)d_in[13];
    float* out = (float*)d_out;

    float *qlat, *qbuf, *kvpe, *kvlat, *kvb, *ybuf;
    cudaGetSymbolAddress((void**)&qlat,  g_qlat);
    cudaGetSymbolAddress((void**)&qbuf,  g_q);
    cudaGetSymbolAddress((void**)&kvpe,  g_kvpe);
    cudaGetSymbolAddress((void**)&kvlat, g_kvlat);
    cudaGetSymbolAddress((void**)&kvb,   g_kvb);
    cudaGetSymbolAddress((void**)&ybuf,  g_y);

    cudaFuncSetAttribute(gemm_tc<4,4>, cudaFuncAttributeMaxDynamicSharedMemorySize, gsmem(4,4));
    cudaFuncSetAttribute(gemm_tc<4,2>, cudaFuncAttributeMaxDynamicSharedMemorySize, gsmem(4,2));
    cudaFuncSetAttribute(gemm_tc<2,2>, cudaFuncAttributeMaxDynamicSharedMemorySize, gsmem(2,2));
    cudaFuncSetAttribute(attn_tc, cudaFuncAttributeMaxDynamicSharedMemorySize, ATTN_SMEM);

    // Q path
    gemm_tc<4,2><<<dim3(RQ / 64, TT / 128), 256, gsmem(4,2)>>>(x, wq_a, bq_a, qlat, CC);
    rmsnorm_kernel<<<TT, 256>>>(qlat, RQ, qlat, RQ, q_norm_w, RQ);
    gemm_tc<4,4><<<dim3((HH * QKD) / 128, TT / 128), 256, gsmem(4,4)>>>(qlat, wq_b, bq_b, qbuf, RQ);
    rope_q_kernel<<<(TT * HH * 32 + 255) / 256, 256>>>(freqs);

    // KV path
    gemm_tc<2,2><<<dim3((RKV + DR) / 64, TT / 64), 256, gsmem(2,2)>>>(x, wkv_a, bkv_a, kvpe, CC);
    rope_k_kernel<<<(TT * 32 + 255) / 256, 256>>>(freqs);
    rmsnorm_kernel<<<TT, 256>>>(kvpe, RKV + DR, kvlat, RKV, kv_norm_w, RKV);
    gemm_tc<4,4><<<dim3((HH * 256) / 128, TT / 128), 256, gsmem(4,4)>>>(kvlat, wkv_b, bkv_b, kvb, RKV);

    // Attention
    attn_tc<<<dim3(TT / 64, HH), 256, ATTN_SMEM>>>(qbuf, kvb, kvpe, ybuf);

    // Output projection
    gemm_tc<4,2><<<dim3(CC / 64, TT / 128), 256, gsmem(4,2)>>>(ybuf, wo, bo, out, CC);
}

// round 7
// speedup vs baseline: 1.1939x; 1.0609x over previous
#include <cuda_runtime.h>
#include <cstdint>
#include <math.h>

#define TT 2048
#define CC 2048
#define HH 16
#define DN 128
#define DR 64
#define DV 128
#define QKD 192
#define RQ 1536
#define RKV 512
#define EPSF 1e-6f
#define SCALEF 0.07216878364870323f  // 192^-0.5

// ---------------- scratch (device globals; no allocation allowed) ----------------
__device__ float g_qlat[TT * RQ];
__device__ float g_q[TT * HH * QKD];
__device__ float g_kvpe[TT * (RKV + DR)];
__device__ float g_kvlat[TT * RKV];
__device__ float g_kvb[TT * HH * (DN + DV)];
__device__ float g_y[TT * CC];

// ---------------- helpers ----------------
__device__ __forceinline__ float tf32r(float f) {
    unsigned u;
    asm("cvt.rna.tf32.f32 %0, %1;" : "=r"(u) : "f"(f));
    return __uint_as_float(u);
}
__device__ __forceinline__ unsigned fbits(float f) { return __float_as_uint(f); }
__device__ __forceinline__ unsigned ldt(const float* p) { return fbits(tf32r(*p)); }

__device__ __forceinline__ void mma_tf32(float c[4], const unsigned a[4], const unsigned b[2]) {
    asm volatile(
        "mma.sync.aligned.m16n8k8.row.col.f32.tf32.tf32.f32 "
        "{%0,%1,%2,%3}, {%4,%5,%6,%7}, {%8,%9}, {%0,%1,%2,%3};"
        : "+f"(c[0]), "+f"(c[1]), "+f"(c[2]), "+f"(c[3])
        : "r"(a[0]), "r"(a[1]), "r"(a[2]), "r"(a[3]), "r"(b[0]), "r"(b[1]));
}

__device__ __forceinline__ void cpa16(float* s, const float* g) {
    unsigned sa = (unsigned)__cvta_generic_to_shared(s);
    asm volatile("cp.async.cg.shared.global [%0], [%1], 16;" :: "r"(sa), "l"(g) : "memory");
}
__device__ __forceinline__ void cp_commit() { asm volatile("cp.async.commit_group;" ::: "memory"); }
template <int N>
__device__ __forceinline__ void cp_wait() { asm volatile("cp.async.wait_group %0;" :: "n"(N) : "memory"); }

// ---------------- tensor-core GEMM: C[M,N] = A[M,K] @ B[N,K]^T + bias ----------------
// Block 128 x (16*NF), 128 threads (4 warps, 2x2 grid), warp tile 64 x (8*NF).
// 3-stage cp.async pipeline, K staged 32; rna cvt at fragment-load time.
#define GPIT 36

template <int NF>
__global__ void __launch_bounds__(128, 2) gemm_tc(
    const float* __restrict__ A, const float* __restrict__ B,
    const float* __restrict__ bias, float* __restrict__ Cm,
    int K)
{
    constexpr int BM = 128, BN = 16 * NF;
    constexpr int ASTAGE = BM * GPIT, BSTAGE = BN * GPIT;

    extern __shared__ float sh[];
    float* As = sh;
    float* Bs = sh + 3 * ASTAGE;

    int tid = threadIdx.x;
    int lane = tid & 31, warp = tid >> 5;
    int wm = warp >> 1, wn = warp & 1;
    int m0 = blockIdx.y * BM, n0 = blockIdx.x * BN;
    int N = gridDim.x * BN;

    auto load_stage = [&](int s, int k0) {
#pragma unroll
        for (int i = 0; i < (BM * 8) / 128; i++) {
            int idx = i * 128 + tid, r = idx >> 3, c = (idx & 7) << 2;
            cpa16(As + s * ASTAGE + r * GPIT + c, A + (size_t)(m0 + r) * K + k0 + c);
        }
#pragma unroll
        for (int i = 0; i < (BN * 8) / 128; i++) {
            int idx = i * 128 + tid, r = idx >> 3, c = (idx & 7) << 2;
            cpa16(Bs + s * BSTAGE + r * GPIT + c, B + (size_t)(n0 + r) * K + k0 + c);
        }
    };

    float acc[4][NF][4];
#pragma unroll
    for (int i = 0; i < 4; i++)
#pragma unroll
        for (int j = 0; j < NF; j++)
#pragma unroll
            for (int k = 0; k < 4; k++) acc[i][j][k] = 0.f;

    load_stage(0, 0); cp_commit();
    load_stage(1, 32); cp_commit();

    int nIter = K >> 5;
    for (int it = 0; it < nIter; it++) {
        cp_wait<1>();
        __syncthreads();
        if (it + 2 < nIter) load_stage((it + 2) % 3, (it + 2) << 5);
        cp_commit();

        const float* Ab = As + (it % 3) * ASTAGE;
        const float* Bb = Bs + (it % 3) * BSTAGE;
#pragma unroll
        for (int ks = 0; ks < 4; ks++) {
            int kidx = ks * 8 + (lane & 3);
            unsigned af[4][4], bf[NF][2];
            int arow = wm * 64 + (lane >> 2);
#pragma unroll
            for (int mf = 0; mf < 4; mf++) {
                const float* p = Ab + (arow + mf * 16) * GPIT + kidx;
                af[mf][0] = ldt(p);
                af[mf][1] = ldt(p + 8 * GPIT);
                af[mf][2] = ldt(p + 4);
                af[mf][3] = ldt(p + 8 * GPIT + 4);
            }
            int brow = wn * (NF * 8) + (lane >> 2);
#pragma unroll
            for (int nf = 0; nf < NF; nf++) {
                const float* p = Bb + (brow + nf * 8) * GPIT + kidx;
                bf[nf][0] = ldt(p);
                bf[nf][1] = ldt(p + 4);
            }
#pragma unroll
            for (int mf = 0; mf < 4; mf++)
#pragma unroll
                for (int nf = 0; nf < NF; nf++)
                    mma_tf32(acc[mf][nf], af[mf], bf[nf]);
        }
    }

#pragma unroll
    for (int mf = 0; mf < 4; mf++) {
        int row0 = m0 + wm * 64 + mf * 16 + (lane >> 2);
#pragma unroll
        for (int nf = 0; nf < NF; nf++) {
            int col = n0 + wn * (NF * 8) + nf * 8 + 2 * (lane & 3);
            float b0 = bias[col], b1 = bias[col + 1];
            *(float2*)&Cm[(size_t)row0 * N + col] =
                make_float2(acc[mf][nf][0] + b0, acc[mf][nf][1] + b1);
            *(float2*)&Cm[(size_t)(row0 + 8) * N + col] =
                make_float2(acc[mf][nf][2] + b0, acc[mf][nf][3] + b1);
        }
    }
}

static inline int gsmem(int NF) { return 3 * (128 + 16 * NF) * GPIT * 4; }

// ---------------- RMSNorm (row-wise) ----------------
__global__ void __launch_bounds__(256) rmsnorm_kernel(
    const float* __restrict__ src, int srcStride,
    float* __restrict__ dst, int dstStride,
    const float* __restrict__ w, int cols)
{
    int row = blockIdx.x;
    const float* s = src + (size_t)row * srcStride;
    float* d = dst + (size_t)row * dstStride;
    float sum = 0.f;
    for (int i = threadIdx.x; i < cols; i += 256) { float v = s[i]; sum += v * v; }
    __shared__ float red[256];
    red[threadIdx.x] = sum;
    __syncthreads();
    for (int o = 128; o > 0; o >>= 1) {
        if (threadIdx.x < o) red[threadIdx.x] += red[threadIdx.x + o];
        __syncthreads();
    }
    float inv = rsqrtf(red[0] / (float)cols + EPSF);
    for (int i = threadIdx.x; i < cols; i += 256) d[i] = s[i] * inv * w[i];
}

// ---------------- RoPE ----------------
__global__ void rope_q_kernel(const float* __restrict__ freqs) {
    int idx = blockIdx.x * blockDim.x + threadIdx.x;
    if (idx >= TT * HH * 32) return;
    int i = idx & 31;
    int h = (idx >> 5) & 15;
    int t = idx >> 9;
    float f = freqs[t * 32 + i];
    float c = cosf(f), s = sinf(f);
    float* p = g_q + (size_t)t * (HH * QKD) + h * QKD + DN + 2 * i;
    float x0 = p[0], x1 = p[1];
    p[0] = x0 * c - x1 * s;
    p[1] = x0 * s + x1 * c;
}

__global__ void rope_k_kernel(const float* __restrict__ freqs) {
    int idx = blockIdx.x * blockDim.x + threadIdx.x;
    if (idx >= TT * 32) return;
    int i = idx & 31;
    int t = idx >> 5;
    float f = freqs[t * 32 + i];
    float c = cosf(f), s = sinf(f);
    float* p = g_kvpe + (size_t)t * (RKV + DR) + RKV + 2 * i;
    float x0 = p[0], x1 = p[1];
    p[0] = x0 * c - x1 * s;
    p[1] = x0 * s + x1 * c;
}

// ---------------- Flash attention (mma.sync tf32, cp.async double-buffered) ----------------
#define AQ (64 * 192)
#define AV (64 * 128)
#define APP 68
#define ATTN_FLOATS (3 * AQ + 2 * AV + 64 * APP + 192)
#define ATTN_SMEM (ATTN_FLOATS * 4)

__global__ void __launch_bounds__(256, 1) attn_tc(
    const float* __restrict__ q, const float* __restrict__ kvb,
    const float* __restrict__ kvpe, float* __restrict__ y)
{
    extern __shared__ float sm[];
    float* Qs = sm;
    float* Ks = sm + AQ;
    float* Vs = sm + 3 * AQ;
    float* Ps = sm + 3 * AQ + 2 * AV;
    float* m_s = Ps + 64 * APP;
    float* l_s = m_s + 64;
    float* al_s = l_s + 64;

    int h = blockIdx.y;
    int qt = gridDim.x - 1 - blockIdx.x;
    int tid = threadIdx.x, lane = tid & 31, warp = tid >> 5;
    int wm = warp >> 1, wn = warp & 1;

    int lr = tid >> 2;
    int lq = tid & 3;

    auto load_kv = [&](int buf, int kt2) {
        int t = kt2 * 64 + lr;
        const float* gk = kvb + (size_t)t * 4096 + h * 256;
        const float* gp = kvpe + (size_t)t * 576 + 512;
        float* Kb = Ks + buf * AQ + lr * 192;
        int sw = 4 * (lr & 7);
#pragma unroll
        for (int j = 0; j < 12; j++) {
            int c4 = lq * 12 + j;
            const float* src = (c4 < 32) ? (gk + 4 * c4) : (gp + 4 * (c4 - 32));
            cpa16(&Kb[(4 * c4) ^ sw], src);
        }
        float* Vb = Vs + buf * AV + lr * 128;
        int swv = 8 * (lr & 3);
#pragma unroll
        for (int j = 0; j < 8; j++) {
            int c4 = lq * 8 + j;
            cpa16(&Vb[(4 * c4) ^ swv], gk + 128 + 4 * c4);
        }
    };

    {
        const float* gq = q + (size_t)(qt * 64 + lr) * (HH * QKD) + h * QKD;
        float* Qr = Qs + lr * 192;
        int sw = 4 * (lr & 7);
#pragma unroll
        for (int j = 0; j < 12; j++) {
            int c4 = lq * 12 + j;
            cpa16(&Qr[(4 * c4) ^ sw], gq + 4 * c4);
        }
    }
    load_kv(0, 0);
    cp_commit();

    if (tid < 64) { m_s[tid] = -1e30f; l_s[tid] = 0.f; }

    float oacc[8][4];
#pragma unroll
    for (int i = 0; i < 8; i++)
#pragma unroll
        for (int j = 0; j < 4; j++) oacc[i][j] = 0.f;

    for (int kt = 0; kt <= qt; kt++) {
        cp_wait<0>();
        __syncthreads();
        if (kt < qt) load_kv((kt + 1) & 1, kt + 1);
        cp_commit();

        const float* Kb = Ks + (kt & 1) * AQ;
        const float* Vb = Vs + (kt & 1) * AV;

        float sacc[4][4];
#pragma unroll
        for (int i = 0; i < 4; i++)
#pragma unroll
            for (int j = 0; j < 4; j++) sacc[i][j] = 0.f;

        {
            int r0 = wm * 16 + (lane >> 2);
            int swa = 4 * ((lane >> 2) & 7);
            const float* Aq0 = Qs + r0 * 192;
            const float* Aq8 = Qs + (r0 + 8) * 192;
#pragma unroll 4
            for (int k0 = 0; k0 < QKD; k0 += 8) {
                int k = k0 + (lane & 3);
                unsigned a[4];
                a[0] = ldt(&Aq0[k ^ swa]);
                a[1] = ldt(&Aq8[k ^ swa]);
                a[2] = ldt(&Aq0[(k + 4) ^ swa]);
                a[3] = ldt(&Aq8[(k + 4) ^ swa]);
#pragma unroll
                for (int nf = 0; nf < 4; nf++) {
                    const float* pb = Kb + (wn * 32 + nf * 8 + (lane >> 2)) * 192;
                    unsigned b[2] = { ldt(&pb[k ^ swa]), ldt(&pb[(k + 4) ^ swa]) };
                    mma_tf32(sacc[nf], a, b);
                }
            }
        }
#pragma unroll
        for (int nf = 0; nf < 4; nf++) {
            int r = wm * 16 + (lane >> 2);
            int c = wn * 32 + nf * 8 + 2 * (lane & 3);
            Ps[r * APP + c] = sacc[nf][0];
            Ps[r * APP + c + 1] = sacc[nf][1];
            Ps[(r + 8) * APP + c] = sacc[nf][2];
            Ps[(r + 8) * APP + c + 1] = sacc[nf][3];
        }
        __syncthreads();

        {
            int row = tid >> 2, sub = tid & 3;
            float* pr = Ps + row * APP + sub * 16;
            bool diag = (kt == qt);
            float v[16];
#pragma unroll
            for (int j = 0; j < 16; j++) {
                float x = pr[j];
                if (diag && (sub * 16 + j) > row) x = -1e30f;
                v[j] = x;
            }
            float mx = v[0];
#pragma unroll
            for (int j = 1; j < 16; j++) mx = fmaxf(mx, v[j]);
            mx = fmaxf(mx, __shfl_xor_sync(0xffffffffu, mx, 1));
            mx = fmaxf(mx, __shfl_xor_sync(0xffffffffu, mx, 2));
            float mo = m_s[row];
            float mn = fmaxf(mo, mx);
            float sum = 0.f;
#pragma unroll
            for (int j = 0; j < 16; j++) {
                float p = __expf((v[j] - mn) * SCALEF);
                sum += p;
                pr[j] = tf32r(p);
            }
            sum += __shfl_xor_sync(0xffffffffu, sum, 1);
            sum += __shfl_xor_sync(0xffffffffu, sum, 2);
            if (sub == 0) {
                float al = __expf((mo - mn) * SCALEF);
                al_s[row] = al;
                l_s[row] = l_s[row] * al + sum;
                m_s[row] = mn;
            }
        }
        __syncthreads();

        {
            int r0 = wm * 16 + (lane >> 2);
            float al0 = al_s[r0], al1 = al_s[r0 + 8];
#pragma unroll
            for (int nf = 0; nf < 8; nf++) {
                oacc[nf][0] *= al0; oacc[nf][1] *= al0;
                oacc[nf][2] *= al1; oacc[nf][3] *= al1;
            }
            const float* Ap0 = Ps + r0 * APP + (lane & 3);
            int swv = 8 * (lane & 3);
#pragma unroll
            for (int k0 = 0; k0 < 64; k0 += 8) {
                unsigned a[4];
                a[0] = fbits(Ap0[k0]);
                a[1] = fbits(Ap0[k0 + 8 * APP]);
                a[2] = fbits(Ap0[k0 + 4]);
                a[3] = fbits(Ap0[k0 + 4 + 8 * APP]);
                int kr = k0 + (lane & 3);
                const float* Vr0 = Vb + kr * 128;
                const float* Vr4 = Vb + (kr + 4) * 128;
#pragma unroll
                for (int nf = 0; nf < 8; nf++) {
                    int col = wn * 64 + nf * 8 + (lane >> 2);
                    unsigned b[2] = { ldt(&Vr0[col ^ swv]), ldt(&Vr4[col ^ swv]) };
                    mma_tf32(oacc[nf], a, b);
                }
            }
        }
    }

    {
        int r0 = wm * 16 + (lane >> 2);
        float inv0 = 1.f / l_s[r0], inv1 = 1.f / l_s[r0 + 8];
        int t0 = qt * 64 + r0;
#pragma unroll
        for (int nf = 0; nf < 8; nf++) {
            int c = wn * 64 + nf * 8 + 2 * (lane & 3);
            float* y0 = y + (size_t)t0 * CC + h * DV + c;
            float* y1 = y + (size_t)(t0 + 8) * CC + h * DV + c;
            y0[0] = oacc[nf][0] * inv0;
            y0[1] = oacc[nf][1] * inv0;
            y1[0] = oacc[nf][2] * inv1;
            y1[1] = oacc[nf][3] * inv1;
        }
    }
}

// ---------------- launch ----------------
extern "C" void kernel_launch(void* const* d_in, const int* in_sizes, int n_in,
                              void* d_out, int out_size) {
    const float* x        = (const float*)d_in[0];
    const float* freqs    = (const float*)d_in[1];
    const float* wq_a     = (const float*)d_in[2];
    const float* bq_a     = (const float*)d_in[3];
    const float* q_norm_w = (const float*)d_in[4];
    const float* wq_b     = (const float*)d_in[5];
    const float* bq_b     = (const float*)d_in[6];
    const float* wkv_a    = (const float*)d_in[7];
    const float* bkv_a    = (const float*)d_in[8];
    const float* kv_norm_w= (const float*)d_in[9];
    const float* wkv_b    = (const float*)d_in[10];
    const float* bkv_b    = (const float*)d_in[11];
    const float* wo       = (const float*)d_in[12];
    const float* bo       = (const float*)d_in[13];
    float* out = (float*)d_out;

    float *qlat, *qbuf, *kvpe, *kvlat, *kvb, *ybuf;
    cudaGetSymbolAddress((void**)&qlat,  g_qlat);
    cudaGetSymbolAddress((void**)&qbuf,  g_q);
    cudaGetSymbolAddress((void**)&kvpe,  g_kvpe);
    cudaGetSymbolAddress((void**)&kvlat, g_kvlat);
    cudaGetSymbolAddress((void**)&kvb,   g_kvb);
    cudaGetSymbolAddress((void**)&ybuf,  g_y);

    cudaFuncSetAttribute(gemm_tc<8>, cudaFuncAttributeMaxDynamicSharedMemorySize, gsmem(8));
    cudaFuncSetAttribute(gemm_tc<4>, cudaFuncAttributeMaxDynamicSharedMemorySize, gsmem(4));
    cudaFuncSetAttribute(attn_tc,    cudaFuncAttributeMaxDynamicSharedMemorySize, ATTN_SMEM);

    // Q path
    gemm_tc<8><<<dim3(RQ / 128, TT / 128), 128, gsmem(8)>>>(x, wq_a, bq_a, qlat, CC);
    rmsnorm_kernel<<<TT, 256>>>(qlat, RQ, qlat, RQ, q_norm_w, RQ);
    gemm_tc<8><<<dim3((HH * QKD) / 128, TT / 128), 128, gsmem(8)>>>(qlat, wq_b, bq_b, qbuf, RQ);
    rope_q_kernel<<<(TT * HH * 32 + 255) / 256, 256>>>(freqs);

    // KV path
    gemm_tc<4><<<dim3((RKV + DR) / 64, TT / 128), 128, gsmem(4)>>>(x, wkv_a, bkv_a, kvpe, CC);
    rope_k_kernel<<<(TT * 32 + 255) / 256, 256>>>(freqs);
    rmsnorm_kernel<<<TT, 256>>>(kvpe, RKV + DR, kvlat, RKV, kv_norm_w, RKV);
    gemm_tc<8><<<dim3((HH * 256) / 128, TT / 128), 128, gsmem(8)>>>(kvlat, wkv_b, bkv_b, kvb, RKV);

    // Attention
    attn_tc<<<dim3(TT / 64, HH), 256, ATTN_SMEM>>>(qbuf, kvb, kvpe, ybuf);

    // Output projection
    gemm_tc<8><<<dim3(CC / 128, TT / 128), 128, gsmem(8)>>>(ybuf, wo, bo, out, CC);
}